// round 1
// baseline (speedup 1.0000x reference)
#include <cuda_runtime.h>
#include <cuda_bf16.h>
#include <cstdint>

// WatermarkLayer: 50 Adam steps per row, one warp per row, all state in registers.
//
// Key facts derived from the reference:
//  - cos_theta resolves to exactly 1.0f in fp32 (bisection boundary analysis),
//    so hinge = ||mu|| - dot.
//  - gradient of LAMBDA_W * mean(relu(norm*ct - dot)) w.r.t. mu_ij:
//      g = (1/B) * [hinge>0] * (mu_j/||mu|| - w_j)
//  - losses[-1] = loss evaluated at step t=50 PRE-update (mu still gets 50 updates).
//  - Output layout: [mu_wm (B*D), log_var (B*D), loss (1)], all fp32.

#define DLAT 512
#define EPL 16        // elements per lane (512 / 32)
#define NSTEPS 50
#define MAXB 131072

__device__ float g_rowloss[MAXB];

__device__ __forceinline__ float rcp_fast(float x)  { float y; asm("rcp.approx.f32 %0, %1;"   : "=f"(y) : "f"(x)); return y; }
__device__ __forceinline__ float sqrt_fast(float x) { float y; asm("sqrt.approx.f32 %0, %1;"  : "=f"(y) : "f"(x)); return y; }
__device__ __forceinline__ float rsqrt_fast(float x){ float y; asm("rsqrt.approx.f32 %0, %1;" : "=f"(y) : "f"(x)); return y; }

__global__ __launch_bounds__(256, 1)
void wm_adam_kernel(const float* __restrict__ mu,
                    const float* __restrict__ carrier,
                    float* __restrict__ out_mu,
                    float* __restrict__ rowloss,
                    int B)
{
    const int warp = (blockIdx.x * blockDim.x + threadIdx.x) >> 5;
    const int lane = threadIdx.x & 31;
    if (warp >= B) return;

    // Load this row (16 floats/lane via 4x float4, coalesced) and the carrier.
    const float4* murow = reinterpret_cast<const float4*>(mu + (size_t)warp * DLAT);
    const float4* wrow  = reinterpret_cast<const float4*>(carrier);

    float mu_[EPL], w_[EPL], m_[EPL], v_[EPL];
    #pragma unroll
    for (int k = 0; k < 4; k++) {
        float4 a = murow[lane + 32 * k];
        float4 b = wrow[lane + 32 * k];
        mu_[4*k+0] = a.x; mu_[4*k+1] = a.y; mu_[4*k+2] = a.z; mu_[4*k+3] = a.w;
        w_[4*k+0]  = b.x; w_[4*k+1]  = b.y; w_[4*k+2]  = b.z; w_[4*k+3]  = b.w;
    }
    #pragma unroll
    for (int i = 0; i < EPL; i++) { m_[i] = 0.0f; v_[i] = 0.0f; }

    const float invB = 1.0f / (float)B;   // B is a power of two -> exact
    float pb1 = 1.0f, pb2 = 1.0f;         // running B1^t, B2^t
    float lossv = 0.0f;

    #pragma unroll 1
    for (int t = 1; t <= NSTEPS; t++) {
        pb1 *= 0.9f;
        pb2 *= 0.999f;
        const float lrbc1 = 0.01f * rcp_fast(1.0f - pb1);  // LR / (1 - B1^t)
        const float bc2   = rcp_fast(1.0f - pb2);          // 1 / (1 - B2^t)

        // dot(mu, w) and ||mu||^2 via per-lane partials + butterfly reduce
        float dot = 0.0f, nsq = 0.0f;
        #pragma unroll
        for (int i = 0; i < EPL; i++) {
            dot = fmaf(mu_[i], w_[i], dot);
            nsq = fmaf(mu_[i], mu_[i], nsq);
        }
        #pragma unroll
        for (int o = 16; o > 0; o >>= 1) {
            dot += __shfl_xor_sync(0xFFFFFFFFu, dot, o);
            nsq += __shfl_xor_sync(0xFFFFFFFFu, nsq, o);
        }

        const float rn    = rsqrt_fast(nsq);
        const float norm  = nsq * rn;            // ||mu||
        const float hinge = norm - dot;          // cos_theta == 1.0f exactly

        float p, q;
        if (hinge > 0.0f) { p = invB * rn; q = invB; lossv = hinge; }
        else              { p = 0.0f;      q = 0.0f; lossv = 0.0f;  }
        // after the loop, lossv == relu(hinge) at t == NSTEPS (pre-update)

        #pragma unroll
        for (int i = 0; i < EPL; i++) {
            const float g  = fmaf(p, mu_[i], -(q * w_[i]));      // (1/B)(mu/|mu| - w)
            m_[i] = fmaf(0.9f,   m_[i], 0.1f   * g);
            v_[i] = fmaf(0.999f, v_[i], 0.001f * (g * g));
            const float vh  = v_[i] * bc2;
            const float den = sqrt_fast(vh) + 1e-8f;
            mu_[i] = fmaf(-(m_[i] * lrbc1), rcp_fast(den), mu_[i]);
        }
    }

    // Write optimized row
    float4* outrow = reinterpret_cast<float4*>(out_mu + (size_t)warp * DLAT);
    #pragma unroll
    for (int k = 0; k < 4; k++) {
        float4 a;
        a.x = mu_[4*k+0]; a.y = mu_[4*k+1]; a.z = mu_[4*k+2]; a.w = mu_[4*k+3];
        outrow[lane + 32 * k] = a;
    }
    if (lane == 0) rowloss[warp] = lossv;
}

// Deterministic single-block reduction: loss = mean(rowloss)
__global__ __launch_bounds__(1024)
void wm_reduce_loss(const float* __restrict__ rowloss, float* __restrict__ out, int B)
{
    __shared__ float sh[1024];
    float s = 0.0f;
    for (int i = threadIdx.x; i < B; i += 1024) s += rowloss[i];
    sh[threadIdx.x] = s;
    __syncthreads();
    #pragma unroll
    for (int o = 512; o > 0; o >>= 1) {
        if (threadIdx.x < o) sh[threadIdx.x] += sh[threadIdx.x + o];
        __syncthreads();
    }
    if (threadIdx.x == 0) out[0] = sh[0] * (1.0f / (float)B);
}

extern "C" void kernel_launch(void* const* d_in, const int* in_sizes, int n_in,
                              void* d_out, int out_size)
{
    const float* mu      = (const float*)d_in[0];
    const float* log_var = (const float*)d_in[1];
    const float* carrier = (const float*)d_in[2];
    float* out = (float*)d_out;

    const int B = in_sizes[0] / DLAT;          // 131072
    float* out_mu   = out;                      // [B*D]
    float* out_lv   = out + (size_t)B * DLAT;   // [B*D]
    float* out_loss = out + (size_t)out_size - 1;

    float* rowloss;
    cudaGetSymbolAddress((void**)&rowloss, g_rowloss);

    // log_var passthrough
    cudaMemcpyAsync(out_lv, log_var, (size_t)B * DLAT * sizeof(float),
                    cudaMemcpyDeviceToDevice, 0);

    // main per-row Adam kernel: 8 warps/block, one warp per row
    const int blocks = (B + 7) / 8;
    wm_adam_kernel<<<blocks, 256>>>(mu, carrier, out_mu, rowloss, B);

    // loss = mean over rows of relu(hinge @ t=50)
    wm_reduce_loss<<<1, 1024>>>(rowloss, out_loss, B);
}